// round 1
// baseline (speedup 1.0000x reference)
#include <cuda_runtime.h>

#define NB 8
#define NA 120000
#define NM 64
#define TPB 256

__device__ float g_cls[NB];
__device__ float g_reg[NB];
__device__ int   g_pos[NB];

__global__ void rn_init_kernel() {
    int i = threadIdx.x;
    if (i < NB) { g_cls[i] = 0.f; g_reg[i] = 0.f; g_pos[i] = 0; }
}

__global__ __launch_bounds__(TPB) void rn_loss_kernel(
    const float* __restrict__ gt,     // (B, M, 5): cx, cy, w, h, label
    const float* __restrict__ pcls,   // (B, A, 1)
    const float* __restrict__ preg,   // (B, A, 4)
    const float* __restrict__ anc)    // (1, A, 4): x1, y1, x2, y2
{
    __shared__ float4 s_corn[NM];   // gt corners x1,y1,x2,y2
    __shared__ float  s_area[NM];   // gt area (corner-derived, matches ref rounding)
    __shared__ float4 s_raw[NM];    // gt cx,cy,w,h (for regression targets)
    __shared__ float  s_lab[NM];
    __shared__ int    s_ngt;
    __shared__ float  s_c[TPB / 32], s_r[TPB / 32];
    __shared__ int    s_n[TPB / 32];

    const int img = blockIdx.y;
    const int tid = threadIdx.x;

    if (tid == 0) s_ngt = 0;
    if (tid < NM) {
        const float* g = gt + ((long)img * NM + tid) * 5;
        float cx = g[0], cy = g[1], w = g[2], h = g[3], lab = g[4];
        float x1 = cx - 0.5f * w, y1 = cy - 0.5f * h;
        float x2 = cx + 0.5f * w, y2 = cy + 0.5f * h;
        s_corn[tid] = make_float4(x1, y1, x2, y2);
        s_area[tid] = (x2 - x1) * (y2 - y1);
        s_raw[tid]  = make_float4(cx, cy, w, h);
        s_lab[tid]  = lab;
    }
    __syncthreads();
    // valid labels form a prefix (index < ngt) by construction
    if (tid < NM && s_lab[tid] != -1.0f) atomicAdd(&s_ngt, 1);
    __syncthreads();
    const int ngt = s_ngt;   // >= 1

    const int a = blockIdx.x * TPB + tid;

    float cterm = 0.f, rterm = 0.f;
    int   npos  = 0;

    if (a < NA) {
        const float4 A4 = __ldg((const float4*)anc + a);
        const float aw = A4.z - A4.x;
        const float ah = A4.w - A4.y;
        const float Ca = aw * ah;

        // running best (I_b, S_b, m_b); iou_m = I_m / (S_m - I_m)
        float Ib, Sb;
        int   mb = 0;
        {
            float4 gq = s_corn[0];
            float w = fminf(A4.z, gq.z) - fmaxf(A4.x, gq.x);
            float h = fminf(A4.w, gq.w) - fmaxf(A4.y, gq.y);
            w = fmaxf(w, 0.f); h = fmaxf(h, 0.f);
            Ib = w * h;
            Sb = Ca + s_area[0];
        }
        #pragma unroll 4
        for (int m = 1; m < ngt; ++m) {
            float4 gq = s_corn[m];
            float w = fminf(A4.z, gq.z) - fmaxf(A4.x, gq.x);
            float h = fminf(A4.w, gq.w) - fmaxf(A4.y, gq.y);
            w = fmaxf(w, 0.f); h = fmaxf(h, 0.f);
            float I = w * h;
            float S = Ca + s_area[m];
            // I/(S-I) > Ib/(Sb-Ib)  <=>  I*Sb > Ib*S   (denominators > 0)
            if (I * Sb > Ib * S) { Ib = I; Sb = S; mb = m; }
        }

        // iou_max >= 0.5 <=> 3*Ib >= Sb ;  iou_max < 0.4 <=> 7*Ib < 2*Sb
        const bool pos = (3.0f * Ib >= Sb);
        const bool neg = (7.0f * Ib < 2.0f * Sb);

        const float p = __ldg(pcls + (long)img * NA + a);

        if (pos) {
            npos = 1;
            const float lab = s_lab[mb];
            if (lab == 0.0f) {   // one-hot hit at class 0 (C == 1)
                float q = 1.0f - p;
                cterm = 0.25f * q * q * (-logf(p));
            } else {
                cterm = 0.75f * p * p * (-logf(1.0f - p));
            }

            // regression (smooth-L1, beta = 1/9), only for positive anchors
            const float acx = A4.x + 0.5f * aw;
            const float acy = A4.y + 0.5f * ah;
            const float4 gr = s_raw[mb];
            const float gw = fmaxf(gr.z, 1.0f);
            const float gh = fmaxf(gr.w, 1.0f);
            const float t0 = ((gr.x - acx) / aw) / 0.1f;
            const float t1 = ((gr.y - acy) / ah) / 0.1f;
            const float t2 = logf(gw / aw) / 0.2f;
            const float t3 = logf(gh / ah) / 0.2f;

            const float4 rg = __ldg((const float4*)preg + (long)img * NA + a);
            const float d0 = fabsf(t0 - rg.x);
            const float d1 = fabsf(t1 - rg.y);
            const float d2 = fabsf(t2 - rg.z);
            const float d3 = fabsf(t3 - rg.w);
            const float TH = (float)(1.0 / 9.0);
            const float CC = (float)(0.5 / 9.0);
            rterm  = (d0 <= TH) ? 4.5f * d0 * d0 : d0 - CC;
            rterm += (d1 <= TH) ? 4.5f * d1 * d1 : d1 - CC;
            rterm += (d2 <= TH) ? 4.5f * d2 * d2 : d2 - CC;
            rterm += (d3 <= TH) ? 4.5f * d3 * d3 : d3 - CC;
        } else if (neg) {
            cterm = 0.75f * p * p * (-logf(1.0f - p));
        }
        // 0.4 <= iou < 0.5: ignore (contributes nothing)
    }

    // warp reduction
    const unsigned mask = 0xFFFFFFFFu;
    #pragma unroll
    for (int off = 16; off; off >>= 1) {
        cterm += __shfl_down_sync(mask, cterm, off);
        rterm += __shfl_down_sync(mask, rterm, off);
        npos  += __shfl_down_sync(mask, npos, off);
    }
    const int wid = tid >> 5, lid = tid & 31;
    if (lid == 0) { s_c[wid] = cterm; s_r[wid] = rterm; s_n[wid] = npos; }
    __syncthreads();
    if (tid == 0) {
        float c = 0.f, r = 0.f; int n = 0;
        #pragma unroll
        for (int i = 0; i < TPB / 32; ++i) { c += s_c[i]; r += s_r[i]; n += s_n[i]; }
        atomicAdd(&g_cls[img], c);
        atomicAdd(&g_reg[img], r);
        atomicAdd(&g_pos[img], n);
    }
}

__global__ void rn_final_kernel(float* __restrict__ out) {
    if (threadIdx.x == 0) {
        float cs = 0.f, rs = 0.f;
        #pragma unroll
        for (int i = 0; i < NB; ++i) {
            float np = (float)g_pos[i];
            cs += g_cls[i] / fmaxf(np, 1.0f);
            rs += (g_pos[i] > 0) ? (g_reg[i] / fmaxf(np * 4.0f, 1.0f)) : 0.0f;
        }
        out[0] = cs / (float)NB;
        out[1] = rs / (float)NB;
    }
}

extern "C" void kernel_launch(void* const* d_in, const int* in_sizes, int n_in,
                              void* d_out, int out_size) {
    const float* gt = (const float*)d_in[0];   // y_true_tmp (8,64,5)
    const float* pc = (const float*)d_in[1];   // y_classifs (8,120000,1)
    const float* pr = (const float*)d_in[2];   // y_regressions (8,120000,4)
    const float* an = (const float*)d_in[3];   // anchors (1,120000,4)

    rn_init_kernel<<<1, 32>>>();
    dim3 grid((NA + TPB - 1) / TPB, NB);
    rn_loss_kernel<<<grid, TPB>>>(gt, pc, pr, an);
    rn_final_kernel<<<1, 32>>>((float*)d_out);
}